// round 1
// baseline (speedup 1.0000x reference)
#include <cuda_runtime.h>
#include <cstdint>
#include <cstddef>

#define THREADS 256
#define TILE 64
#define FS 68           // padded feature-row stride (floats)
#define EK 268          // edge feature dim
#define NK 96           // node feature dim
#define DC 128          // output channels

__constant__ int c_EPa[16] = {1,1,2,1,0,1,3,2,2,0,2,3,0,0,3,3};
__constant__ int c_EPb[16] = {1,2,1,0,1,3,1,2,0,2,3,2,0,3,0,3};
__constant__ int c_NPa[6]  = {1,1,1,0,0,3};
__constant__ int c_NPb[6]  = {0,2,3,2,3,2};
__constant__ int c_ORD[4]  = {1,0,2,3};

__device__ __forceinline__ void norm3g(float& x, float& y, float& z) {
    float n = sqrtf(x*x + y*y + z*z);
    n = (n == 0.0f) ? 1.0f : n;
    float inv = 1.0f / n;
    x *= inv; y *= inv; z *= inv;
}

__device__ __forceinline__ unsigned long long pack2(float a) {
    unsigned long long r;
    unsigned int ai = __float_as_uint(a);
    asm("mov.b64 %0, {%1, %1};" : "=l"(r) : "r"(ai));
    return r;
}

__device__ __forceinline__ void fma2(unsigned long long& d,
                                     unsigned long long a,
                                     unsigned long long b) {
    asm("fma.rn.f32x2 %0, %1, %2, %0;" : "+l"(d) : "l"(a), "l"(b));
}

// ---------------------------------------------------------------------------
// Edge kernel: persistent, handles both E_in and E_ex tile streams.
// ---------------------------------------------------------------------------
__global__ void __launch_bounds__(THREADS, 1)
edge_kernel(const float* __restrict__ X,
            const int* __restrict__ idxA, const int* __restrict__ idxB,
            const float* __restrict__ Wg, const float* __restrict__ bg,
            const float* __restrict__ gg, const float* __restrict__ betag,
            float* __restrict__ outA, float* __restrict__ outB,
            int E, int N)
{
    extern __shared__ float sm[];
    float* Wsm = sm;                 // [EK][DC] transposed weights
    float* F   = Wsm + EK * DC;      // [EK][FS] transposed features
    float* sB  = F + EK * FS;        // bias (linear)
    float* sG  = sB + DC;            // gain
    float* sBe = sG + DC;            // LN bias

    const int tid = threadIdx.x;

    for (int i = tid; i < EK * DC; i += THREADS) {
        int k = i >> 7, c = i & 127;
        Wsm[i] = Wg[c * EK + k];
    }
    if (tid < DC) { sB[tid] = bg[tid]; sG[tid] = gg[tid]; sBe[tid] = betag[tid]; }
    __syncthreads();

    const int tilesPer = (E + TILE - 1) / TILE;
    const int totTiles = 2 * tilesPer;

    const int j     = tid & 3;        // pair-thread within edge
    const int eloc  = tid >> 2;       // edge within tile (feature phase)
    const int cidx  = tid & 31;       // channel group (GEMM phase)
    const int eg    = tid >> 5;       // edge group (warp id)
    const int eBase = eg * 8;
    const int c0    = cidx * 4;

    const float DMU = 20.0f / 15.0f;

    for (int tile = blockIdx.x; tile < totTiles; tile += gridDim.x) {
        const int which = (tile >= tilesPer);
        const int* idx  = which ? idxB : idxA;
        float* outp     = which ? outB : outA;
        const int base  = (which ? (tile - tilesPer) : tile) * TILE;

        // ---------------- feature phase ----------------
        {
            const int e = base + eloc;
            if (e < E) {
                const int src = idx[e];
                const int dst = idx[E + e];
                const float* Sx = X + (size_t)src * 12;
                const float* Dx = X + (size_t)dst * 12;
                #pragma unroll
                for (int pp = 0; pp < 4; pp++) {
                    const int p = j + pp * 4;
                    const float* sa = Sx + c_EPa[p] * 3;
                    const float* db = Dx + c_EPb[p] * 3;
                    float dx = sa[0] - db[0];
                    float dy = sa[1] - db[1];
                    float dz = sa[2] - db[2];
                    float D = sqrtf(dx*dx + dy*dy + dz*dz + 1e-6f);
                    float* frow = F + (p * 16) * FS + eloc;
                    #pragma unroll
                    for (int i = 0; i < 16; i++) {
                        float t = (D - (float)i * DMU) * 0.8f;
                        frow[i * FS] = __expf(-t * t);
                    }
                }
                if (j == 0) {
                    float s0x = Sx[0], s0y = Sx[1], s0z = Sx[2];
                    float q0x=0.f,q0y=0.f,q0z=0.f;
                    float q1x=0.f,q1y=0.f,q1z=0.f;
                    float q2x=0.f,q2y=0.f,q2z=0.f;
                    if (src != N - 1) {
                        float s1x=Sx[3], s1y=Sx[4], s1z=Sx[5];
                        float s2x=Sx[6], s2y=Sx[7], s2z=Sx[8];
                        float u0x=s1x-s0x, u0y=s1y-s0y, u0z=s1z-s0z;
                        norm3g(u0x,u0y,u0z);
                        float u1x=s2x-s1x, u1y=s2y-s1y, u1z=s2z-s1z;
                        norm3g(u1x,u1y,u1z);
                        float nx = u0y*u1z - u0z*u1y;
                        float ny = u0z*u1x - u0x*u1z;
                        float nz = u0x*u1y - u0y*u1x;
                        norm3g(nx,ny,nz);
                        float bx = u0x-u1x, by = u0y-u1y, bz = u0z-u1z;
                        norm3g(bx,by,bz);
                        float cx = by*nz - bz*ny;
                        float cy = bz*nx - bx*nz;
                        float cz = bx*ny - by*nx;
                        q0x=bx; q0y=by; q0z=bz;
                        q1x=nx; q1y=ny; q1z=nz;
                        q2x=cx; q2y=cy; q2z=cz;
                    }
                    #pragma unroll
                    for (int a = 0; a < 4; a++) {
                        const float* da = Dx + c_ORD[a] * 3;
                        float dxx = da[0]-s0x, dxy = da[1]-s0y, dxz = da[2]-s0z;
                        float vx = q0x*dxx + q1x*dxy + q2x*dxz;
                        float vy = q0y*dxx + q1y*dxy + q2y*dxz;
                        float vz = q0z*dxx + q1z*dxy + q2z*dxz;
                        norm3g(vx,vy,vz);
                        float* fr = F + (256 + a * 3) * FS + eloc;
                        fr[0]      = vx;
                        fr[FS]     = vy;
                        fr[2 * FS] = vz;
                    }
                }
            }
        }
        __syncthreads();

        // ---------------- GEMM phase (f32x2) ----------------
        unsigned long long acc[4][4];
        #pragma unroll
        for (int q = 0; q < 4; q++)
            #pragma unroll
            for (int cc = 0; cc < 4; cc++)
                acc[q][cc] = 0ull;

        #pragma unroll 4
        for (int k = 0; k < EK; k++) {
            const ulonglong2* fp =
                reinterpret_cast<const ulonglong2*>(F + k * FS + eBase);
            ulonglong2 fa = fp[0];
            ulonglong2 fb = fp[1];
            const float4 w = *reinterpret_cast<const float4*>(Wsm + k * DC + c0);
            unsigned long long w0 = pack2(w.x);
            unsigned long long w1 = pack2(w.y);
            unsigned long long w2 = pack2(w.z);
            unsigned long long w3 = pack2(w.w);
            unsigned long long f2[4] = {fa.x, fa.y, fb.x, fb.y};
            #pragma unroll
            for (int q = 0; q < 4; q++) {
                fma2(acc[q][0], f2[q], w0);
                fma2(acc[q][1], f2[q], w1);
                fma2(acc[q][2], f2[q], w2);
                fma2(acc[q][3], f2[q], w3);
            }
        }

        // ---------------- epilogue: bias + LN + store ----------------
        float v[8][4];
        #pragma unroll
        for (int q = 0; q < 4; q++)
            #pragma unroll
            for (int cc = 0; cc < 4; cc++) {
                union { unsigned long long u; float2 f; } cv;
                cv.u = acc[q][cc];
                v[2*q][cc]   = cv.f.x;
                v[2*q+1][cc] = cv.f.y;
            }
        const float b0 = sB[c0],  b1 = sB[c0+1],  b2 = sB[c0+2],  b3 = sB[c0+3];
        const float g0 = sG[c0],  g1 = sG[c0+1],  g2 = sG[c0+2],  g3 = sG[c0+3];
        const float t0 = sBe[c0], t1 = sBe[c0+1], t2 = sBe[c0+2], t3 = sBe[c0+3];

        #pragma unroll
        for (int s = 0; s < 8; s++) {
            float x0 = v[s][0] + b0;
            float x1 = v[s][1] + b1;
            float x2 = v[s][2] + b2;
            float x3 = v[s][3] + b3;
            float sum = x0 + x1 + x2 + x3;
            #pragma unroll
            for (int m = 16; m > 0; m >>= 1)
                sum += __shfl_xor_sync(0xffffffffu, sum, m);
            float mu = sum * (1.0f / 128.0f);
            float d0 = x0 - mu, d1 = x1 - mu, d2 = x2 - mu, d3 = x3 - mu;
            float sq = d0*d0 + d1*d1 + d2*d2 + d3*d3;
            #pragma unroll
            for (int m = 16; m > 0; m >>= 1)
                sq += __shfl_xor_sync(0xffffffffu, sq, m);
            float inv = 1.0f / (sqrtf(sq * (1.0f / 127.0f) + 1e-6f) + 1e-6f);
            const int e2 = base + eBase + s;
            if (e2 < E) {
                float4 o;
                o.x = g0 * d0 * inv + t0;
                o.y = g1 * d1 * inv + t1;
                o.z = g2 * d2 * inv + t2;
                o.w = g3 * d3 * inv + t3;
                *reinterpret_cast<float4*>(outp + (size_t)e2 * DC + c0) = o;
            }
        }
        __syncthreads();   // protect F before next tile's feature writes
    }
}

// ---------------------------------------------------------------------------
// Node kernel: one block per 64-node tile.
// ---------------------------------------------------------------------------
__global__ void __launch_bounds__(THREADS, 1)
node_kernel(const float* __restrict__ X,
            const float* __restrict__ Wg, const float* __restrict__ bg,
            const float* __restrict__ gg, const float* __restrict__ betag,
            float* __restrict__ out, int N)
{
    extern __shared__ float sm[];
    float* Wsm = sm;               // [NK][DC]
    float* F   = Wsm + NK * DC;    // [NK][FS]
    float* sB  = F + NK * FS;
    float* sG  = sB + DC;
    float* sBe = sG + DC;

    const int tid = threadIdx.x;
    for (int i = tid; i < NK * DC; i += THREADS) {
        int k = i >> 7, c = i & 127;
        Wsm[i] = Wg[c * NK + k];
    }
    if (tid < DC) { sB[tid] = bg[tid]; sG[tid] = gg[tid]; sBe[tid] = betag[tid]; }
    __syncthreads();

    const int j     = tid & 3;
    const int eloc  = tid >> 2;
    const int cidx  = tid & 31;
    const int eg    = tid >> 5;
    const int eBase = eg * 8;
    const int c0    = cidx * 4;
    const int base  = blockIdx.x * TILE;
    const float DMU = 20.0f / 15.0f;

    // features
    {
        const int n = base + eloc;
        if (n < N) {
            const float* Sx = X + (size_t)n * 12;
            #pragma unroll
            for (int pp = 0; pp < 2; pp++) {
                const int p = j + pp * 4;
                if (p < 6) {
                    const float* sa = Sx + c_NPa[p] * 3;
                    const float* sb = Sx + c_NPb[p] * 3;
                    float dx = sa[0] - sb[0];
                    float dy = sa[1] - sb[1];
                    float dz = sa[2] - sb[2];
                    float D = sqrtf(dx*dx + dy*dy + dz*dz + 1e-6f);
                    float* frow = F + (p * 16) * FS + eloc;
                    #pragma unroll
                    for (int i = 0; i < 16; i++) {
                        float t = (D - (float)i * DMU) * 0.8f;
                        frow[i * FS] = __expf(-t * t);
                    }
                }
            }
        }
    }
    __syncthreads();

    // GEMM
    unsigned long long acc[4][4];
    #pragma unroll
    for (int q = 0; q < 4; q++)
        #pragma unroll
        for (int cc = 0; cc < 4; cc++)
            acc[q][cc] = 0ull;

    #pragma unroll 4
    for (int k = 0; k < NK; k++) {
        const ulonglong2* fp =
            reinterpret_cast<const ulonglong2*>(F + k * FS + eBase);
        ulonglong2 fa = fp[0];
        ulonglong2 fb = fp[1];
        const float4 w = *reinterpret_cast<const float4*>(Wsm + k * DC + c0);
        unsigned long long w0 = pack2(w.x);
        unsigned long long w1 = pack2(w.y);
        unsigned long long w2 = pack2(w.z);
        unsigned long long w3 = pack2(w.w);
        unsigned long long f2[4] = {fa.x, fa.y, fb.x, fb.y};
        #pragma unroll
        for (int q = 0; q < 4; q++) {
            fma2(acc[q][0], f2[q], w0);
            fma2(acc[q][1], f2[q], w1);
            fma2(acc[q][2], f2[q], w2);
            fma2(acc[q][3], f2[q], w3);
        }
    }

    // epilogue
    float v[8][4];
    #pragma unroll
    for (int q = 0; q < 4; q++)
        #pragma unroll
        for (int cc = 0; cc < 4; cc++) {
            union { unsigned long long u; float2 f; } cv;
            cv.u = acc[q][cc];
            v[2*q][cc]   = cv.f.x;
            v[2*q+1][cc] = cv.f.y;
        }
    const float b0 = sB[c0],  b1 = sB[c0+1],  b2 = sB[c0+2],  b3 = sB[c0+3];
    const float g0 = sG[c0],  g1 = sG[c0+1],  g2 = sG[c0+2],  g3 = sG[c0+3];
    const float t0 = sBe[c0], t1 = sBe[c0+1], t2 = sBe[c0+2], t3 = sBe[c0+3];

    #pragma unroll
    for (int s = 0; s < 8; s++) {
        float x0 = v[s][0] + b0;
        float x1 = v[s][1] + b1;
        float x2 = v[s][2] + b2;
        float x3 = v[s][3] + b3;
        float sum = x0 + x1 + x2 + x3;
        #pragma unroll
        for (int m = 16; m > 0; m >>= 1)
            sum += __shfl_xor_sync(0xffffffffu, sum, m);
        float mu = sum * (1.0f / 128.0f);
        float d0 = x0 - mu, d1 = x1 - mu, d2 = x2 - mu, d3 = x3 - mu;
        float sq = d0*d0 + d1*d1 + d2*d2 + d3*d3;
        #pragma unroll
        for (int m = 16; m > 0; m >>= 1)
            sq += __shfl_xor_sync(0xffffffffu, sq, m);
        float inv = 1.0f / (sqrtf(sq * (1.0f / 127.0f) + 1e-6f) + 1e-6f);
        const int n2 = base + eBase + s;
        if (n2 < N) {
            float4 o;
            o.x = g0 * d0 * inv + t0;
            o.y = g1 * d1 * inv + t1;
            o.z = g2 * d2 * inv + t2;
            o.w = g3 * d3 * inv + t3;
            *reinterpret_cast<float4*>(out + (size_t)n2 * DC + c0) = o;
        }
    }
}

extern "C" void kernel_launch(void* const* d_in, const int* in_sizes, int n_in,
                              void* d_out, int out_size)
{
    const float* X  = (const float*)d_in[0];
    const int*   Ein = (const int*)d_in[1];
    const int*   Eex = (const int*)d_in[2];
    const float* nW = (const float*)d_in[3];
    const float* nb = (const float*)d_in[4];
    const float* eW = (const float*)d_in[5];
    const float* eb = (const float*)d_in[6];
    const float* gn = (const float*)d_in[7];
    const float* bn = (const float*)d_in[8];
    const float* ge = (const float*)d_in[9];
    const float* be = (const float*)d_in[10];

    const int N = in_sizes[0] / 12;
    const int E = in_sizes[1] / 2;

    float* out   = (float*)d_out;
    float* outV  = out;
    float* outIn = out + (size_t)N * DC;
    float* outEx = outIn + (size_t)E * DC;

    const size_t smE = (size_t)(EK * DC + EK * FS + 3 * DC) * sizeof(float);
    const size_t smN = (size_t)(NK * DC + NK * FS + 3 * DC) * sizeof(float);
    cudaFuncSetAttribute(edge_kernel,
                         cudaFuncAttributeMaxDynamicSharedMemorySize, (int)smE);
    cudaFuncSetAttribute(node_kernel,
                         cudaFuncAttributeMaxDynamicSharedMemorySize, (int)smN);

    int sms = 148;
    cudaDeviceGetAttribute(&sms, cudaDevAttrMultiProcessorCount, 0);

    const int nTiles = (N + TILE - 1) / TILE;
    node_kernel<<<nTiles, THREADS, smN>>>(X, nW, nb, gn, bn, outV, N);
    edge_kernel<<<sms, THREADS, smE>>>(X, Ein, Eex, eW, eb, ge, be,
                                       outIn, outEx, E, N);
}

// round 8
// speedup vs baseline: 1.9696x; 1.9696x over previous
#include <cuda_runtime.h>
#include <cstdint>
#include <cstddef>

// ===================== edge kernel (mma.sync tf32) =========================
#define THREADS_E 256
#define TILE_E    128
#define EK        268
#define KPAD      272
#define NKS       34            // total k-steps (K=8 each)
#define KS0       18            // chunk0 k-steps  (k 0..143)
#define KS1       16            // chunk1 k-steps  (k 144..271)
#define DC        128
#define MPAD      136           // A buffer row stride (mod 32 == 8)
#define SSTRIDE   132           // staging row stride

// smem layout (bytes)
#define BPACK_FLTS (NKS * 16 * 32 * 2)         // 34816 floats = 139264 B
#define ABUF_FLTS  (KS0 * 8 * MPAD)            // 19584 floats = 78336 B
#define BPACK_OFF  0
#define ABUF_OFF   (BPACK_FLTS * 4)
#define PAR_OFF    (ABUF_OFF + ABUF_FLTS * 4)
#define SMEM_E     (PAR_OFF + 3 * 128 * 4)     // 219136 B total

__device__ __forceinline__ uint32_t to_tf32(float f) {
    uint32_t r;
    asm("cvt.rna.tf32.f32 %0, %1;" : "=r"(r) : "f"(f));
    return r;
}

__device__ __forceinline__ void mma_tf32(float& d0, float& d1, float& d2, float& d3,
                                         uint32_t a0, uint32_t a1, uint32_t a2, uint32_t a3,
                                         uint32_t b0, uint32_t b1) {
    asm volatile("mma.sync.aligned.m16n8k8.row.col.f32.tf32.tf32.f32 "
                 "{%0,%1,%2,%3},{%4,%5,%6,%7},{%8,%9},{%0,%1,%2,%3};"
                 : "+f"(d0), "+f"(d1), "+f"(d2), "+f"(d3)
                 : "r"(a0), "r"(a1), "r"(a2), "r"(a3), "r"(b0), "r"(b1));
}

__device__ __forceinline__ void norm3g(float& x, float& y, float& z) {
    float n = sqrtf(x*x + y*y + z*z);
    n = (n == 0.0f) ? 1.0f : n;
    float inv = 1.0f / n;
    x *= inv; y *= inv; z *= inv;
}

__global__ void __launch_bounds__(THREADS_E, 1)
edge_kernel_mma(const float* __restrict__ X,
                const int* __restrict__ idxA, const int* __restrict__ idxB,
                const float* __restrict__ Wg, const float* __restrict__ bg,
                const float* __restrict__ gg, const float* __restrict__ betag,
                float* __restrict__ outA, float* __restrict__ outB,
                int E, int N)
{
    constexpr int EPa[16] = {1,1,2,1,0,1,3,2,2,0,2,3,0,0,3,3};
    constexpr int EPb[16] = {1,2,1,0,1,3,1,2,0,2,3,2,0,3,0,3};
    constexpr int ORD[4]  = {1,0,2,3};

    extern __shared__ char smem[];
    uint32_t* Bp  = (uint32_t*)(smem + BPACK_OFF);   // packed tf32 weights
    uint32_t* Au  = (uint32_t*)(smem + ABUF_OFF);    // tf32 feature buffer
    float*    stg = (float*)(smem + ABUF_OFF);       // staging (reuses Au)
    float*    sB  = (float*)(smem + PAR_OFF);
    float*    sG  = sB + 128;
    float*    sBe = sG + 128;

    const int tid  = threadIdx.x;
    const int lane = tid & 31;
    const int wid  = tid >> 5;

    // ---- init: pack weights (tf32, fragment-ordered), params ----
    for (int i = tid; i < NKS * 16 * 32; i += THREADS_E) {
        const int l  = i & 31;
        const int nt = (i >> 5) & 15;
        const int ks = i >> 9;
        const int n  = nt * 8 + (l >> 2);
        const int k0 = ks * 8 + (l & 3);
        const int k1 = k0 + 4;
        float w0 = (k0 < EK) ? Wg[n * EK + k0] : 0.0f;
        float w1 = (k1 < EK) ? Wg[n * EK + k1] : 0.0f;
        Bp[i * 2 + 0] = to_tf32(w0);
        Bp[i * 2 + 1] = to_tf32(w1);
    }
    if (tid < 128) { sB[tid] = bg[tid]; sG[tid] = gg[tid]; sBe[tid] = betag[tid]; }
    __syncthreads();

    // GEMM role constants: warp grid 4 (M) x 2 (N)
    const int wm = wid >> 1;          // 0..3  -> m band of 32
    const int wn = wid & 1;           // 0..1  -> n band of 64
    const int m0 = wm * 32;           // FIX: lane row offset lives in Ath only
    const uint32_t* Ath = Au + (lane & 3) * MPAD + (lane >> 2);

    const int tilesPer = (E + TILE_E - 1) / TILE_E;
    const int totTiles = 2 * tilesPer;
    const float DMU = 20.0f / 15.0f;

    const int eP = tid & 127;         // producer edge
    const int hP = tid >> 7;          // producer half (0/1)

    for (int tile = blockIdx.x; tile < totTiles; tile += gridDim.x) {
        const int which = (tile >= tilesPer);
        const int* idx  = which ? idxB : idxA;
        float* outp     = which ? outB : outA;
        const int base  = (which ? (tile - tilesPer) : tile) * TILE_E;

        // ---- gather X for producer edge ----
        const int egl = base + eP;
        const int e   = (egl < E) ? egl : (E - 1);
        const int src = idx[e];
        const int dst = idx[E + e];
        const float4* Sp4 = (const float4*)(X + (size_t)src * 12);
        const float4* Dp4 = (const float4*)(X + (size_t)dst * 12);
        float4 s0 = Sp4[0], s1 = Sp4[1], s2 = Sp4[2];
        float4 dd0 = Dp4[0], dd1 = Dp4[1], dd2 = Dp4[2];
        float S[12]  = {s0.x,s0.y,s0.z,s0.w,s1.x,s1.y,s1.z,s1.w,s2.x,s2.y,s2.z,s2.w};
        float Dv[12] = {dd0.x,dd0.y,dd0.z,dd0.w,dd1.x,dd1.y,dd1.z,dd1.w,dd2.x,dd2.y,dd2.z,dd2.w};

        float acc[2][8][4];
        #pragma unroll
        for (int i = 0; i < 2; i++)
            #pragma unroll
            for (int j = 0; j < 8; j++)
                #pragma unroll
                for (int c = 0; c < 4; c++) acc[i][j][c] = 0.0f;

        // ================= two K-chunks =================
        #pragma unroll
        for (int ch = 0; ch < 2; ch++) {
            const int pLo = ch ? 9 : 0;           // pair range for this chunk
            const int kBase = ch ? 144 : 0;
            const int nks   = ch ? KS1 : KS0;

            // ---- produce features for this chunk ----
            {
                const int pS = ch ? (hP ? 12 : 9)  : (hP ? 5 : 0);
                const int pE = ch ? (hP ? 16 : 12) : (hP ? 9 : 5);
                for (int p = pS; p < pE; p++) {
                    const float* sa = S  + EPa[p] * 3;
                    const float* db = Dv + EPb[p] * 3;
                    float dx = sa[0]-db[0], dy = sa[1]-db[1], dz = sa[2]-db[2];
                    float Dd = sqrtf(dx*dx + dy*dy + dz*dz + 1e-6f);
                    uint32_t* row = Au + (p * 16 - kBase) * MPAD + eP;
                    #pragma unroll
                    for (int i = 0; i < 16; i++) {
                        float t = (Dd - (float)i * DMU) * 0.8f;
                        row[i * MPAD] = to_tf32(__expf(-t * t));
                    }
                }
                if (ch == 1) {
                    if (hP == 0) {
                        // directions -> buffer rows 112..123
                        float q0x=0.f,q0y=0.f,q0z=0.f,q1x=0.f,q1y=0.f,q1z=0.f,
                              q2x=0.f,q2y=0.f,q2z=0.f;
                        if (src != N - 1) {
                            float u0x=S[3]-S[0], u0y=S[4]-S[1], u0z=S[5]-S[2];
                            norm3g(u0x,u0y,u0z);
                            float u1x=S[6]-S[3], u1y=S[7]-S[4], u1z=S[8]-S[5];
                            norm3g(u1x,u1y,u1z);
                            float nx=u0y*u1z-u0z*u1y, ny=u0z*u1x-u0x*u1z, nz=u0x*u1y-u0y*u1x;
                            norm3g(nx,ny,nz);
                            float bx=u0x-u1x, by=u0y-u1y, bz=u0z-u1z;
                            norm3g(bx,by,bz);
                            float cx=by*nz-bz*ny, cy=bz*nx-bx*nz, cz=bx*ny-by*nx;
                            q0x=bx;q0y=by;q0z=bz; q1x=nx;q1y=ny;q1z=nz; q2x=cx;q2y=cy;q2z=cz;
                        }
                        uint32_t* dbase = Au + 112 * MPAD + eP;
                        #pragma unroll
                        for (int a = 0; a < 4; a++) {
                            const float* da = Dv + ORD[a] * 3;
                            float xx=da[0]-S[0], xy=da[1]-S[1], xz=da[2]-S[2];
                            float vx=q0x*xx+q1x*xy+q2x*xz;
                            float vy=q0y*xx+q1y*xy+q2y*xz;
                            float vz=q0z*xx+q1z*xy+q2z*xz;
                            norm3g(vx,vy,vz);
                            dbase[(a*3+0)*MPAD] = to_tf32(vx);
                            dbase[(a*3+1)*MPAD] = to_tf32(vy);
                            dbase[(a*3+2)*MPAD] = to_tf32(vz);
                        }
                    } else {
                        // zero pad rows 124..127 (cols 0..135)
                        for (int i = eP; i < 4 * MPAD; i += 128) {
                            Au[124 * MPAD + i] = 0u;
                        }
                    }
                }
            }
            __syncthreads();

            // ---- GEMM over this chunk ----
            const uint32_t* Bth = Bp + ((pLo ? (KS0*16) : 0) + wn * 8) * 64 + lane * 2;
            #pragma unroll 2
            for (int ksl = 0; ksl < nks; ksl++) {
                const uint32_t* ap = Ath + ksl * (8 * MPAD) + m0;
                uint32_t a[2][4];
                #pragma unroll
                for (int i = 0; i < 2; i++) {
                    const uint32_t* q = ap + i * 16;
                    a[i][0] = q[0];
                    a[i][1] = q[8];
                    a[i][2] = q[4 * MPAD];
                    a[i][3] = q[4 * MPAD + 8];
                }
                const uint32_t* bp = Bth + ksl * (16 * 64);
                #pragma unroll
                for (int j = 0; j < 8; j++) {
                    uint2 b = *(const uint2*)(bp + j * 64);
                    mma_tf32(acc[0][j][0], acc[0][j][1], acc[0][j][2], acc[0][j][3],
                             a[0][0], a[0][1], a[0][2], a[0][3], b.x, b.y);
                    mma_tf32(acc[1][j][0], acc[1][j][1], acc[1][j][2], acc[1][j][3],
                             a[1][0], a[1][1], a[1][2], a[1][3], b.x, b.y);
                }
            }
            __syncthreads();   // chunk done; producers may overwrite Au
        }

        // ================= epilogue =================
        // stage C fragments into stg (reuses Au memory)
        {
            #pragma unroll
            for (int i = 0; i < 2; i++) {
                const int m = wm * 32 + i * 16 + (lane >> 2);
                #pragma unroll
                for (int j = 0; j < 8; j++) {
                    const int n = wn * 64 + j * 8 + (lane & 3) * 2;
                    *(float2*)(stg + m * SSTRIDE + n)       =
                        make_float2(acc[i][j][0], acc[i][j][1]);
                    *(float2*)(stg + (m + 8) * SSTRIDE + n) =
                        make_float2(acc[i][j][2], acc[i][j][3]);
                }
            }
        }
        __syncthreads();

        // LN: 2 threads per edge (64 channels each)
        {
            const int er   = tid >> 1;         // row in tile
            const int half = tid & 1;
            float* row = stg + er * SSTRIDE + half * 64;
            float v[64];
            float sum = 0.0f;
            #pragma unroll
            for (int c = 0; c < 64; c += 4) {
                float4 x = *(const float4*)(row + c);
                v[c+0] = x.x + sB[half*64 + c+0];
                v[c+1] = x.y + sB[half*64 + c+1];
                v[c+2] = x.z + sB[half*64 + c+2];
                v[c+3] = x.w + sB[half*64 + c+3];
                sum += v[c+0] + v[c+1] + v[c+2] + v[c+3];
            }
            sum += __shfl_xor_sync(0xffffffffu, sum, 1);
            float mu = sum * (1.0f / 128.0f);
            float sq = 0.0f;
            #pragma unroll
            for (int c = 0; c < 64; c++) {
                float d = v[c] - mu;
                v[c] = d;
                sq += d * d;
            }
            sq += __shfl_xor_sync(0xffffffffu, sq, 1);
            float inv = 1.0f / (sqrtf(sq * (1.0f / 127.0f) + 1e-6f) + 1e-6f);
            #pragma unroll
            for (int c = 0; c < 64; c += 4) {
                float4 o;
                o.x = sG[half*64 + c+0] * v[c+0] * inv + sBe[half*64 + c+0];
                o.y = sG[half*64 + c+1] * v[c+1] * inv + sBe[half*64 + c+1];
                o.z = sG[half*64 + c+2] * v[c+2] * inv + sBe[half*64 + c+2];
                o.w = sG[half*64 + c+3] * v[c+3] * inv + sBe[half*64 + c+3];
                *(float4*)(row + c) = o;
            }
        }
        __syncthreads();

        // coalesced store
        {
            const int c0 = (tid & 31) * 4;
            const int r0 = tid >> 5;
            #pragma unroll
            for (int i = 0; i < 16; i++) {
                const int r = r0 + i * 8;
                const int eo = base + r;
                if (eo < E) {
                    float4 x = *(const float4*)(stg + r * SSTRIDE + c0);
                    *(float4*)(outp + (size_t)eo * DC + c0) = x;
                }
            }
        }
        __syncthreads();   // protect stg/Au before next tile
    }
}

// ===================== node kernel (fp32 f32x2) ============================
#define THREADS_N 256
#define TILE_N 64
#define FSN 68
#define NK 96

__device__ __forceinline__ unsigned long long pack2(float a) {
    unsigned long long r;
    unsigned int ai = __float_as_uint(a);
    asm("mov.b64 %0, {%1, %1};" : "=l"(r) : "r"(ai));
    return r;
}
__device__ __forceinline__ void fma2(unsigned long long& d,
                                     unsigned long long a,
                                     unsigned long long b) {
    asm("fma.rn.f32x2 %0, %1, %2, %0;" : "+l"(d) : "l"(a), "l"(b));
}

__global__ void __launch_bounds__(THREADS_N, 1)
node_kernel(const float* __restrict__ X,
            const float* __restrict__ Wg, const float* __restrict__ bg,
            const float* __restrict__ gg, const float* __restrict__ betag,
            float* __restrict__ out, int N)
{
    constexpr int NPa[6] = {1,1,1,0,0,3};
    constexpr int NPb[6] = {0,2,3,2,3,2};
    extern __shared__ float sm[];
    float* Wsm = sm;
    float* F   = Wsm + NK * DC;
    float* sB  = F + NK * FSN;
    float* sG  = sB + DC;
    float* sBe = sG + DC;

    const int tid = threadIdx.x;
    for (int i = tid; i < NK * DC; i += THREADS_N) {
        int k = i >> 7, c = i & 127;
        Wsm[i] = Wg[c * NK + k];
    }
    if (tid < DC) { sB[tid] = bg[tid]; sG[tid] = gg[tid]; sBe[tid] = betag[tid]; }
    __syncthreads();

    const int j    = tid & 3;
    const int eloc = tid >> 2;
    const int cidx = tid & 31;
    const int eg   = tid >> 5;
    const int eBase = eg * 8;
    const int c0   = cidx * 4;
    const int base = blockIdx.x * TILE_N;
    const float DMU = 20.0f / 15.0f;

    {
        const int n = base + eloc;
        if (n < N) {
            const float* Sx = X + (size_t)n * 12;
            #pragma unroll
            for (int pp = 0; pp < 2; pp++) {
                const int p = j + pp * 4;
                if (p < 6) {
                    const float* sa = Sx + NPa[p] * 3;
                    const float* sb = Sx + NPb[p] * 3;
                    float dx = sa[0]-sb[0], dy = sa[1]-sb[1], dz = sa[2]-sb[2];
                    float Dd = sqrtf(dx*dx + dy*dy + dz*dz + 1e-6f);
                    float* frow = F + (p * 16) * FSN + eloc;
                    #pragma unroll
                    for (int i = 0; i < 16; i++) {
                        float t = (Dd - (float)i * DMU) * 0.8f;
                        frow[i * FSN] = __expf(-t * t);
                    }
                }
            }
        }
    }
    __syncthreads();

    unsigned long long acc[4][4];
    #pragma unroll
    for (int q = 0; q < 4; q++)
        #pragma unroll
        for (int cc = 0; cc < 4; cc++) acc[q][cc] = 0ull;

    #pragma unroll 4
    for (int k = 0; k < NK; k++) {
        const ulonglong2* fp = (const ulonglong2*)(F + k * FSN + eBase);
        ulonglong2 fa = fp[0];
        ulonglong2 fb = fp[1];
        const float4 w = *(const float4*)(Wsm + k * DC + c0);
        unsigned long long w0 = pack2(w.x), w1 = pack2(w.y);
        unsigned long long w2 = pack2(w.z), w3 = pack2(w.w);
        unsigned long long f2[4] = {fa.x, fa.y, fb.x, fb.y};
        #pragma unroll
        for (int q = 0; q < 4; q++) {
            fma2(acc[q][0], f2[q], w0);
            fma2(acc[q][1], f2[q], w1);
            fma2(acc[q][2], f2[q], w2);
            fma2(acc[q][3], f2[q], w3);
        }
    }

    float v[8][4];
    #pragma unroll
    for (int q = 0; q < 4; q++)
        #pragma unroll
        for (int cc = 0; cc < 4; cc++) {
            union { unsigned long long u; float2 f; } cv;
            cv.u = acc[q][cc];
            v[2*q][cc]   = cv.f.x;
            v[2*q+1][cc] = cv.f.y;
        }
    const float b0=sB[c0], b1=sB[c0+1], b2=sB[c0+2], b3=sB[c0+3];
    const float g0=sG[c0], g1=sG[c0+1], g2=sG[c0+2], g3=sG[c0+3];
    const float t0=sBe[c0],t1=sBe[c0+1],t2=sBe[c0+2],t3=sBe[c0+3];

    #pragma unroll
    for (int s = 0; s < 8; s++) {
        float x0=v[s][0]+b0, x1=v[s][1]+b1, x2=v[s][2]+b2, x3=v[s][3]+b3;
        float sum = x0+x1+x2+x3;
        #pragma unroll
        for (int m = 16; m > 0; m >>= 1) sum += __shfl_xor_sync(0xffffffffu, sum, m);
        float mu = sum * (1.0f/128.0f);
        float d0=x0-mu, d1=x1-mu, d2=x2-mu, d3=x3-mu;
        float sq = d0*d0+d1*d1+d2*d2+d3*d3;
        #pragma unroll
        for (int m = 16; m > 0; m >>= 1) sq += __shfl_xor_sync(0xffffffffu, sq, m);
        float inv = 1.0f / (sqrtf(sq * (1.0f/127.0f) + 1e-6f) + 1e-6f);
        const int n2 = base + eBase + s;
        if (n2 < N) {
            float4 o;
            o.x = g0*d0*inv + t0;
            o.y = g1*d1*inv + t1;
            o.z = g2*d2*inv + t2;
            o.w = g3*d3*inv + t3;
            *(float4*)(out + (size_t)n2 * DC + c0) = o;
        }
    }
}

// ===================== launch =====================
extern "C" void kernel_launch(void* const* d_in, const int* in_sizes, int n_in,
                              void* d_out, int out_size)
{
    const float* X   = (const float*)d_in[0];
    const int*   Ein = (const int*)d_in[1];
    const int*   Eex = (const int*)d_in[2];
    const float* nW  = (const float*)d_in[3];
    const float* nb  = (const float*)d_in[4];
    const float* eW  = (const float*)d_in[5];
    const float* eb  = (const float*)d_in[6];
    const float* gn  = (const float*)d_in[7];
    const float* bn  = (const float*)d_in[8];
    const float* ge  = (const float*)d_in[9];
    const float* be  = (const float*)d_in[10];

    const int N = in_sizes[0] / 12;
    const int E = in_sizes[1] / 2;

    float* out   = (float*)d_out;
    float* outV  = out;
    float* outIn = out + (size_t)N * DC;
    float* outEx = outIn + (size_t)E * DC;

    const size_t smN = (size_t)(NK * DC + NK * FSN + 3 * DC) * sizeof(float);
    cudaFuncSetAttribute(edge_kernel_mma,
                         cudaFuncAttributeMaxDynamicSharedMemorySize, SMEM_E);
    cudaFuncSetAttribute(node_kernel,
                         cudaFuncAttributeMaxDynamicSharedMemorySize, (int)smN);

    int sms = 148;
    cudaDeviceGetAttribute(&sms, cudaDevAttrMultiProcessorCount, 0);

    const int nTiles = (N + TILE_N - 1) / TILE_N;
    node_kernel<<<nTiles, THREADS_N, smN>>>(X, nW, nb, gn, bn, outV, N);
    edge_kernel_mma<<<sms, THREADS_E, SMEM_E>>>(X, Ein, Eex, eW, eb, ge, be,
                                                outIn, outEx, E, N);
}